// round 9
// baseline (speedup 1.0000x reference)
#include <cuda_runtime.h>
#include <math.h>

#define BATCH   128
#define CCH     16
#define TLEN    40000
#define DIMSEL  8
#define TSTART  6000
#define SEGLEN  8064     /* 14064 - 6000 */
#define KS      64
#define NWIN    8001     /* SEGLEN - KS + 1 */
#define EOUT    32

#define NSLICE  2
#define SLICE_W 4001     /* ceil(8001/2) */
#define NT      256
#define WPT     17       /* gcd(17,32)=1 -> conflict-free scalar LDS */
#define VLEN    (SLICE_W + KS - 1)   /* 4064 valid floats per slice */
#define SSEGPAD 4424     /* max smem idx read = 255*17 + 81 = 4416 */

typedef unsigned long long ull;

#define FMA2(d, a, b, c) \
    asm("fma.rn.f32x2 %0, %1, %2, %3;" : "=l"(d) : "l"(a), "l"(b), "l"(c))
#define ADD2(d, a, c) \
    asm("add.rn.f32x2 %0, %1, %2;" : "=l"(d) : "l"(a), "l"(c))
#define PACK2(d, lo, hi) \
    asm("mov.b64 %0, {%1, %2};" : "=l"(d) : "f"(lo), "f"(hi))
#define UNPACK2(lo, hi, s) \
    asm("mov.b64 {%0, %1}, %2;" : "=f"(lo), "=f"(hi) : "l"(s))

__device__ ull gbest[BATCH];   /* zero-initialized at module load; self-reset */
__device__ int gcount[BATCH];

__device__ __forceinline__ unsigned order_f32(float s) {
    unsigned b = __float_as_uint(s);
    return (b & 0x80000000u) ? ~b : (b | 0x80000000u);
}

__global__ __launch_bounds__(NT, 2)
void shapelet_kernel(const float* __restrict__ x,
                     const float* __restrict__ shp,
                     const float* __restrict__ l1_w,
                     const float* __restrict__ l1_b,
                     const float* __restrict__ l2_w,
                     const float* __restrict__ l2_b,
                     float* __restrict__ out)
{
    __shared__ float  sseg[SSEGPAD];
    __shared__ float  ssh_raw[KS];
    __shared__ float  ssh_c[KS + 1];     /* centered; [64] = 0 pad */
    __shared__ float2 p2sh[KS];          /* p2sh[k] = (sc[k], sc[k+1]) */
    __shared__ float  s_mean_sh;
    __shared__ float  redS[NT / 32];
    __shared__ int    redI[NT / 32];
    __shared__ int    last_flag;
    __shared__ int    widx_sh;

    const int sl   = blockIdx.x;
    const int b    = blockIdx.y;
    const int tid  = threadIdx.x;
    const int lane = tid & 31;
    const int wid  = tid >> 5;

    const int W0       = sl * SLICE_W;
    const int nw_local = min(SLICE_W, NWIN - W0);    /* 4001 / 4000 */

    // ---- stage slice: x[b, DIMSEL, TSTART+W0 : +VLEN] (coalesced scalar) ----
    const float* xb = x + ((size_t)b * CCH + DIMSEL) * TLEN + TSTART;
    const int vl = min(VLEN, SEGLEN - W0);
    for (int i = tid; i < vl; i += NT)           sseg[i] = xb[W0 + i];
    for (int i = vl + tid; i < SSEGPAD; i += NT) sseg[i] = 0.f;
    if (tid < KS) ssh_raw[tid] = shp[tid];
    __syncthreads();

    if (tid == 0) {
        float sm = 0.f;
        #pragma unroll
        for (int k = 0; k < KS; k++) sm += ssh_raw[k];
        s_mean_sh = sm * (1.0f / KS);
        ssh_c[KS] = 0.f;
    }
    __syncthreads();
    if (tid < KS) ssh_c[tid] = ssh_raw[tid] - s_mean_sh;
    __syncthreads();
    if (tid < KS) p2sh[tid] = make_float2(ssh_c[tid], ssh_c[tid + 1]);
    __syncthreads();

    // ---- packed streaming dots: 17 windows/thread, pair chunks of 16 ----
    const int lb = tid * WPT;
    ull dot2[WPT];
    #pragma unroll
    for (int i = 0; i < WPT; i++) dot2[i] = 0ull;
    ull sum2 = 0ull, sq2 = 0ull;

    #pragma unroll
    for (int c = 0; c < 4; c++) {        /* shapelet pairs k in [16c, 16c+16) */
        ull p2r[16];
        #pragma unroll
        for (int m = 0; m < 16; m++)
            p2r[m] = *(const ull*)&p2sh[16 * c + m];  /* broadcast LDS.64 */

        #pragma unroll
        for (int t = 0; t <= 16; t++) {  /* jj in [8c, 8c+16] */
            const int jj = 8 * c + t;
            const float v0 = sseg[lb + 2 * jj];
            const float v1 = sseg[lb + 2 * jj + 1];
            ull vp; PACK2(vp, v0, v1);

            /* fused sum/sumsq over j = 0..63: each jj in [0,32) exactly once */
            if (((c == 0) || (t >= 9)) && (jj < 32)) {
                ADD2(sum2, vp, sum2);
                FMA2(sq2,  vp, vp, sq2);
            }

            #pragma unroll
            for (int i = 0; i < WPT; i++) {
                const int k = 2 * jj - i;            /* compile-time */
                if (k >= 16 * c && k < 16 * c + 16)
                    FMA2(dot2[i], vp, p2r[k - 16 * c], dot2[i]);
            }
        }
    }

    /* odd windows: leading pair k = -1 -> multiplier (0, sc[0]) */
    {
        ull edge; PACK2(edge, 0.0f, ssh_c[0]);
        #pragma unroll
        for (int i = 1; i < WPT; i += 2) {
            const int jj = (i - 1) / 2;
            const float v0 = sseg[lb + 2 * jj];
            const float v1 = sseg[lb + 2 * jj + 1];
            ull vp; PACK2(vp, v0, v1);
            FMA2(dot2[i], vp, edge, dot2[i]);
        }
    }

    // ---- scores with sliding sum/sumsq ----
    float sum, sq;
    {
        float a, bb;
        UNPACK2(a, bb, sum2); sum = a + bb;
        UNPACK2(a, bb, sq2);  sq  = a + bb;
    }
    float best = -INFINITY;
    int   bidx = NWIN;
    #pragma unroll
    for (int i = 0; i < WPT; i++) {
        if (i > 0) {
            const float vo = sseg[lb + i - 1];
            const float vn = sseg[lb + i - 1 + KS];
            sum += vn - vo;
            sq  += fmaf(vn, vn, -vo * vo);
        }
        float dlo, dhi;
        UNPACK2(dlo, dhi, dot2[i]);
        const float dot = dlo + dhi;
        const float den = sq - sum * sum * (1.0f / KS);
        const float scv = dot * rsqrtf(den);         /* NaN on pad -> guarded */
        const int   lw  = lb + i;
        if (lw < nw_local && scv > best) { best = scv; bidx = W0 + lw; }
    }

    // ---- block argmax: warp shfl -> cross-warp ----
    #pragma unroll
    for (int off = 16; off > 0; off >>= 1) {
        const float so = __shfl_xor_sync(0xffffffffu, best, off);
        const int   io = __shfl_xor_sync(0xffffffffu, bidx, off);
        if (so > best || (so == best && io < bidx)) { best = so; bidx = io; }
    }
    if (lane == 0) { redS[wid] = best; redI[wid] = bidx; }
    __syncthreads();

    if (tid < 32) {
        best = (lane < NT / 32) ? redS[lane] : -INFINITY;
        bidx = (lane < NT / 32) ? redI[lane] : NWIN;
        #pragma unroll
        for (int off = 16; off > 0; off >>= 1) {
            const float so = __shfl_xor_sync(0xffffffffu, best, off);
            const int   io = __shfl_xor_sync(0xffffffffu, bidx, off);
            if (so > best || (so == best && io < bidx)) { best = so; bidx = io; }
        }
        if (lane == 0) {
            const unsigned u = order_f32(best);
            const ull packed = ((ull)u << 32) | (ull)(0xFFFFFFFFu - (unsigned)bidx);
            atomicMax(&gbest[b], packed);
            __threadfence();
            const int old = atomicAdd(&gcount[b], 1);
            last_flag = (old == NSLICE - 1) ? 1 : 0;
        }
    }
    __syncthreads();

    // ---- last CTA of this batch: decode winner, head, reset globals ----
    if (last_flag) {
        if (tid == 0) {
            const ull g = atomicOr(&gbest[b], 0ull);     /* coherent read */
            widx_sh = (int)(0xFFFFFFFFu - (unsigned)(g & 0xFFFFFFFFu));
        }
        __syncthreads();
        const int widx = widx_sh;
        if (tid < EOUT) {
            float acc = l1_b[tid] - l2_b[tid];
            const float* w1 = l1_w + tid * KS;
            const float* w2 = l2_w + tid * KS;
            const float* bw = xb + widx;                 /* gmem, L2-hot */
            #pragma unroll
            for (int k = 0; k < KS; k++) {
                acc = fmaf(bw[k],       w1[k], acc);
                acc = fmaf(-ssh_raw[k], w2[k], acc);
            }
            out[b * EOUT + tid] = acc;
        }
        __syncthreads();
        if (tid == 0) { gbest[b] = 0ull; gcount[b] = 0; }  /* ready for replay */
    }
}

extern "C" void kernel_launch(void* const* d_in, const int* in_sizes, int n_in,
                              void* d_out, int out_size)
{
    const float* x    = (const float*)d_in[0];
    const float* shp  = (const float*)d_in[1];
    const float* l1_w = (const float*)d_in[2];
    const float* l1_b = (const float*)d_in[3];
    const float* l2_w = (const float*)d_in[4];
    const float* l2_b = (const float*)d_in[5];
    float* out = (float*)d_out;

    dim3 grid(NSLICE, BATCH);
    shapelet_kernel<<<grid, NT>>>(x, shp, l1_w, l1_b, l2_w, l2_b, out);
}

// round 10
// speedup vs baseline: 1.3137x; 1.3137x over previous
#include <cuda_runtime.h>
#include <math.h>

#define BATCH   128
#define CCH     16
#define TLEN    40000
#define DIMSEL  8
#define TSTART  6000
#define SEGLEN  8064     /* 14064 - 6000 */
#define KS      64
#define NWIN    8001     /* SEGLEN - KS + 1 */
#define EOUT    32
#define NT      512
#define WPT     16       /* base = 16*tid -> 16B aligned, LDS.128 everywhere */

#define NF4     2064     /* logical f4 count; max q read = 4*511+19 = 2063 */
#define SKEW(q) ((q) + ((q) >> 2))          /* bank = (5*l + c) % 8 : conflict-free */
#define SEGF4   (SKEW(NF4 - 1) + 1)         /* 2579 f4 = 41.3 KB */

typedef unsigned long long ull;

#define FMA2(d, a, b, c) \
    asm("fma.rn.f32x2 %0, %1, %2, %3;" : "=l"(d) : "l"(a), "l"(b), "l"(c))
#define ADD2(d, a, c) \
    asm("add.rn.f32x2 %0, %1, %2;" : "=l"(d) : "l"(a), "l"(c))
#define PACK2(d, lo, hi) \
    asm("mov.b64 %0, {%1, %2};" : "=l"(d) : "f"(lo), "f"(hi))
#define UNPACK2(lo, hi, s) \
    asm("mov.b64 {%0, %1}, %2;" : "=f"(lo), "=f"(hi) : "l"(s))

__global__ __launch_bounds__(NT, 1)
void shapelet_kernel(const float* __restrict__ x,
                     const float* __restrict__ shp,
                     const float* __restrict__ l1_w,
                     const float* __restrict__ l1_b,
                     const float* __restrict__ l2_w,
                     const float* __restrict__ l2_b,
                     float* __restrict__ out)
{
    __shared__ float4 seg4[SEGF4];
    __shared__ float  ssh_raw[KS];
    __shared__ float  ssh_c[KS + 1];     /* centered; [64] = 0 pad */
    __shared__ float2 p2sh[KS];          /* p2sh[k] = (sc[k], sc[k+1]) */
    __shared__ float  s_mean_sh;
    __shared__ float  redS[NT / 32];
    __shared__ int    redI[NT / 32];
    __shared__ int    widx_sh;

    const int b    = blockIdx.x;
    const int tid  = threadIdx.x;
    const int lane = tid & 31;
    const int wid  = tid >> 5;

    // ---- stage segment into skewed f4 layout ----
    const float* xb = x + ((size_t)b * CCH + DIMSEL) * TLEN + TSTART;
    const float4* xb4 = (const float4*)xb;          /* offset % 4 floats == 0 */
    #pragma unroll
    for (int i = tid; i < SEGLEN / 4; i += NT)      /* 2016 f4 */
        seg4[SKEW(i)] = xb4[i];
    if (tid < NF4 - SEGLEN / 4)                     /* zero q in [2016, 2064) */
        seg4[SKEW(SEGLEN / 4 + tid)] = make_float4(0.f, 0.f, 0.f, 0.f);
    if (tid < KS) ssh_raw[tid] = shp[tid];
    __syncthreads();

    if (tid == 0) {
        float sm = 0.f;
        #pragma unroll
        for (int k = 0; k < KS; k++) sm += ssh_raw[k];
        s_mean_sh = sm * (1.0f / KS);
        ssh_c[KS] = 0.f;
    }
    __syncthreads();
    if (tid < KS) ssh_c[tid] = ssh_raw[tid] - s_mean_sh;
    __syncthreads();
    if (tid < KS) p2sh[tid] = make_float2(ssh_c[tid], ssh_c[tid + 1]);
    __syncthreads();

    // ---- packed streaming dots: 16 windows/thread, LDS.128 seg reads ----
    const int tb = tid * 4;              /* f4 base; window base = tid*16 */
    ull dot2[WPT];
    #pragma unroll
    for (int i = 0; i < WPT; i++) dot2[i] = 0ull;
    ull sum2 = 0ull, sq2 = 0ull;

    #pragma unroll
    for (int c = 0; c < 4; c++) {        /* shapelet scalars k in [16c, 16c+16) */
        ull p2r[16];
        #pragma unroll
        for (int n = 0; n < 16; n++)
            p2r[n] = *(const ull*)&p2sh[16 * c + n];  /* broadcast LDS.64 */

        #pragma unroll
        for (int mm = 0; mm < 8; mm++) { /* f4 index m = 4c + mm */
            const int m = 4 * c + mm;
            const float4 F = seg4[SKEW(tb + m)];
            ull vp0, vp1;
            PACK2(vp0, F.x, F.y);        /* scalars j = 4m, 4m+1   */
            PACK2(vp1, F.z, F.w);        /* scalars j = 4m+2, 4m+3 */

            /* window-0 sum/sumsq over j=0..63: each m<16 exactly once */
            if ((mm < 4) && (m < 16)) {
                ADD2(sum2, vp0, sum2);  FMA2(sq2, vp0, vp0, sq2);
                ADD2(sum2, vp1, sum2);  FMA2(sq2, vp1, vp1, sq2);
            }

            #pragma unroll
            for (int i = 0; i < WPT; i++) {
                const int k0 = 4 * m - i;            /* compile-time */
                if (k0 >= 16 * c && k0 < 16 * c + 16)
                    FMA2(dot2[i], vp0, p2r[k0 - 16 * c], dot2[i]);
                const int k1 = 4 * m + 2 - i;
                if (k1 >= 16 * c && k1 < 16 * c + 16)
                    FMA2(dot2[i], vp1, p2r[k1 - 16 * c], dot2[i]);
            }
        }
    }

    // ---- scores: window 0, then 4 groups of 4 windows fed by 2 LDS.128 ----
    const int base = tid * WPT;
    float sum, sq;
    {
        float a, bb;
        UNPACK2(a, bb, sum2); sum = a + bb;
        UNPACK2(a, bb, sq2);  sq  = a + bb;
    }
    float best;
    int   bidx;
    {
        float dlo, dhi;
        UNPACK2(dlo, dhi, dot2[0]);
        const float den = sq - sum * sum * (1.0f / KS);
        best = (dlo + dhi) * rsqrtf(den);
        bidx = base;
        if (base >= NWIN) { best = -INFINITY; bidx = NWIN; }
    }
    ull edge; PACK2(edge, 0.0f, ssh_c[0]);

    #pragma unroll
    for (int g = 0; g < 4; g++) {
        const float4 Fo = seg4[SKEW(tb + g)];        /* e = base+4g .. +3   */
        const float4 Fn = seg4[SKEW(tb + 16 + g)];   /* e = base+64+4g .. +3 */

        /* odd-window leading edge: i = 4g+1 (jj=2g), i = 4g+3 (jj=2g+1) */
        ull vp;
        PACK2(vp, Fo.x, Fo.y); FMA2(dot2[4 * g + 1], vp, edge, dot2[4 * g + 1]);
        PACK2(vp, Fo.z, Fo.w); FMA2(dot2[4 * g + 3], vp, edge, dot2[4 * g + 3]);

        const float ov[4] = {Fo.x, Fo.y, Fo.z, Fo.w};
        const float nv[4] = {Fn.x, Fn.y, Fn.z, Fn.w};
        #pragma unroll
        for (int t = 0; t < 4; t++) {
            const int i = 4 * g + 1 + t;
            if (i >= WPT) continue;                  /* g=3,t=3 */
            const float vo = ov[t];
            const float vn = nv[t];
            sum += vn - vo;
            sq  += fmaf(vn, vn, -vo * vo);
            float dlo, dhi;
            UNPACK2(dlo, dhi, dot2[i]);
            const float den = sq - sum * sum * (1.0f / KS);
            const float scv = (dlo + dhi) * rsqrtf(den);  /* NaN on pad: guarded */
            const int   w   = base + i;
            if (w < NWIN && scv > best) { best = scv; bidx = w; }  /* strict > */
        }
    }

    // ---- argmax: warp shfl -> cross-warp ----
    #pragma unroll
    for (int off = 16; off > 0; off >>= 1) {
        const float so = __shfl_xor_sync(0xffffffffu, best, off);
        const int   io = __shfl_xor_sync(0xffffffffu, bidx, off);
        if (so > best || (so == best && io < bidx)) { best = so; bidx = io; }
    }
    if (lane == 0) { redS[wid] = best; redI[wid] = bidx; }
    __syncthreads();

    if (wid == 0) {
        best = (lane < NT / 32) ? redS[lane] : -INFINITY;
        bidx = (lane < NT / 32) ? redI[lane] : NWIN;
        #pragma unroll
        for (int off = 16; off > 0; off >>= 1) {
            const float so = __shfl_xor_sync(0xffffffffu, best, off);
            const int   io = __shfl_xor_sync(0xffffffffu, bidx, off);
            if (so > best || (so == best && io < bidx)) { best = so; bidx = io; }
        }
        if (lane == 0) widx_sh = bidx;
    }
    __syncthreads();
    const int widx = widx_sh;

    // ---- tiny affine head (scalar reads through skewed layout) ----
    if (tid < EOUT) {
        const float* segf = (const float*)seg4;
        float acc = l1_b[tid] - l2_b[tid];
        const float* w1 = l1_w + tid * KS;
        const float* w2 = l2_w + tid * KS;
        #pragma unroll
        for (int k = 0; k < KS; k++) {
            const int e = widx + k;
            acc = fmaf(segf[SKEW(e >> 2) * 4 + (e & 3)], w1[k], acc);
            acc = fmaf(-ssh_raw[k],                      w2[k], acc);
        }
        out[b * EOUT + tid] = acc;
    }
}

extern "C" void kernel_launch(void* const* d_in, const int* in_sizes, int n_in,
                              void* d_out, int out_size)
{
    const float* x    = (const float*)d_in[0];
    const float* shp  = (const float*)d_in[1];
    const float* l1_w = (const float*)d_in[2];
    const float* l1_b = (const float*)d_in[3];
    const float* l2_w = (const float*)d_in[4];
    const float* l2_b = (const float*)d_in[5];
    float* out = (float*)d_out;

    shapelet_kernel<<<BATCH, NT>>>(x, shp, l1_w, l1_b, l2_w, l2_b, out);
}

// round 11
// speedup vs baseline: 1.3202x; 1.0049x over previous
#include <cuda_runtime.h>
#include <math.h>

#define BATCH   128
#define CCH     16
#define TLEN    40000
#define DIMSEL  8
#define TSTART  6000
#define SEGLEN  8064     /* 14064 - 6000 */
#define KS      64
#define NWIN    8001     /* SEGLEN - KS + 1 */
#define EOUT    32
#define NT      512
#define WPT     16       /* base = 16*tid -> 16B aligned, LDS.128 everywhere */

#define NF4     2064     /* logical f4 count; max q read = 4*511+19 = 2063 */
#define SKEW(q) ((q) + ((q) >> 2))          /* read-path bank = (5l+m)%8 : clean */
#define SEGF4   (SKEW(NF4 - 1) + 1)         /* 2579 f4 = 41.3 KB */

typedef unsigned long long ull;

#define FMA2(d, a, b, c) \
    asm("fma.rn.f32x2 %0, %1, %2, %3;" : "=l"(d) : "l"(a), "l"(b), "l"(c))
#define ADD2(d, a, c) \
    asm("add.rn.f32x2 %0, %1, %2;" : "=l"(d) : "l"(a), "l"(c))
#define PACK2(d, lo, hi) \
    asm("mov.b64 %0, {%1, %2};" : "=l"(d) : "f"(lo), "f"(hi))
#define UNPACK2(lo, hi, s) \
    asm("mov.b64 {%0, %1}, %2;" : "=f"(lo), "=f"(hi) : "l"(s))

__global__ __launch_bounds__(NT, 1)
void shapelet_kernel(const float* __restrict__ x,
                     const float* __restrict__ shp,
                     const float* __restrict__ l1_w,
                     const float* __restrict__ l1_b,
                     const float* __restrict__ l2_w,
                     const float* __restrict__ l2_b,
                     float* __restrict__ out)
{
    __shared__ float4 seg4[SEGF4];
    __shared__ float2 p2sh[KS];          /* p2sh[k] = (sc[k], sc[k+1]), sc centered */
    __shared__ float  sc0_sh;            /* sc[0] for odd-window edge */
    __shared__ float  redS[NT / 32];
    __shared__ int    redI[NT / 32];
    __shared__ int    widx_sh;

    const int b    = blockIdx.x;
    const int tid  = threadIdx.x;
    const int lane = tid & 31;
    const int wid  = tid >> 5;

    // ---- phase 0: issue seg LDGs first (DRAM latency window opens) ----
    const float* xb = x + ((size_t)b * CCH + DIMSEL) * TLEN + TSTART;
    const float4* xb4 = (const float4*)xb;          /* offset % 4 floats == 0 */
    float4 ld[4];
    #pragma unroll
    for (int u = 0; u < 4; u++) {
        const int i = tid + u * NT;
        if (i < SEGLEN / 4) ld[u] = xb4[i];         /* 2016 f4 */
    }

    // ---- shapelet prep under the DRAM wait: no reduction, no extra barrier ----
    if (tid < KS) {
        const float4* s4 = (const float4*)shp;
        float4 a4 = s4[0];
        float sx = a4.x, sy = a4.y, sz = a4.z, sw = a4.w;
        #pragma unroll
        for (int m = 1; m < KS / 4; m++) {          /* 16 LDG.128, L1-broadcast */
            const float4 t4 = s4[m];
            sx += t4.x; sy += t4.y; sz += t4.z; sw += t4.w;
        }
        const float mean = (sx + sy + sz + sw) * (1.0f / KS);
        const float a = shp[tid] - mean;
        const float c = (tid < KS - 1) ? (shp[tid + 1] - mean) : 0.f;
        p2sh[tid] = make_float2(a, c);
        if (tid == 0) sc0_sh = a;
    }

    // ---- zero logical tail, store staged seg, ONE barrier ----
    if (tid < NF4 - SEGLEN / 4)                     /* q in [2016, 2064) */
        seg4[SKEW(SEGLEN / 4 + tid)] = make_float4(0.f, 0.f, 0.f, 0.f);
    #pragma unroll
    for (int u = 0; u < 4; u++) {
        const int i = tid + u * NT;
        if (i < SEGLEN / 4) seg4[SKEW(i)] = ld[u];
    }
    __syncthreads();

    // ---- packed streaming dots: 16 windows/thread, LDS.128 seg reads ----
    const int tb = tid * 4;              /* f4 base; window base = tid*16 */
    ull dot2[WPT];
    #pragma unroll
    for (int i = 0; i < WPT; i++) dot2[i] = 0ull;
    ull sum2 = 0ull, sq2 = 0ull;

    #pragma unroll
    for (int c = 0; c < 4; c++) {        /* shapelet scalars k in [16c, 16c+16) */
        ull p2r[16];
        #pragma unroll
        for (int n = 0; n < 16; n++)
            p2r[n] = *(const ull*)&p2sh[16 * c + n];  /* broadcast LDS.64 */

        #pragma unroll
        for (int mm = 0; mm < 8; mm++) { /* f4 index m = 4c + mm */
            const int m = 4 * c + mm;
            const float4 F = seg4[SKEW(tb + m)];
            ull vp0, vp1;
            PACK2(vp0, F.x, F.y);        /* scalars j = 4m, 4m+1   */
            PACK2(vp1, F.z, F.w);        /* scalars j = 4m+2, 4m+3 */

            /* window-0 sum/sumsq over j=0..63: each m<16 exactly once */
            if ((mm < 4) && (m < 16)) {
                ADD2(sum2, vp0, sum2);  FMA2(sq2, vp0, vp0, sq2);
                ADD2(sum2, vp1, sum2);  FMA2(sq2, vp1, vp1, sq2);
            }

            #pragma unroll
            for (int i = 0; i < WPT; i++) {
                const int k0 = 4 * m - i;            /* compile-time */
                if (k0 >= 16 * c && k0 < 16 * c + 16)
                    FMA2(dot2[i], vp0, p2r[k0 - 16 * c], dot2[i]);
                const int k1 = 4 * m + 2 - i;
                if (k1 >= 16 * c && k1 < 16 * c + 16)
                    FMA2(dot2[i], vp1, p2r[k1 - 16 * c], dot2[i]);
            }
        }
    }

    // ---- scores: window 0, then 4 groups of 4 windows fed by 2 LDS.128 ----
    const int base = tid * WPT;
    float sum, sq;
    {
        float a, bb;
        UNPACK2(a, bb, sum2); sum = a + bb;
        UNPACK2(a, bb, sq2);  sq  = a + bb;
    }
    float best;
    int   bidx;
    {
        float dlo, dhi;
        UNPACK2(dlo, dhi, dot2[0]);
        const float den = sq - sum * sum * (1.0f / KS);
        best = (dlo + dhi) * rsqrtf(den);
        bidx = base;
        if (base >= NWIN) { best = -INFINITY; bidx = NWIN; }
    }
    ull edge; PACK2(edge, 0.0f, sc0_sh);

    #pragma unroll
    for (int g = 0; g < 4; g++) {
        const float4 Fo = seg4[SKEW(tb + g)];        /* e = base+4g .. +3    */
        const float4 Fn = seg4[SKEW(tb + 16 + g)];   /* e = base+64+4g .. +3 */

        /* odd-window leading edge: i = 4g+1, 4g+3 */
        ull vp;
        PACK2(vp, Fo.x, Fo.y); FMA2(dot2[4 * g + 1], vp, edge, dot2[4 * g + 1]);
        PACK2(vp, Fo.z, Fo.w); FMA2(dot2[4 * g + 3], vp, edge, dot2[4 * g + 3]);

        const float ov[4] = {Fo.x, Fo.y, Fo.z, Fo.w};
        const float nv[4] = {Fn.x, Fn.y, Fn.z, Fn.w};
        #pragma unroll
        for (int t = 0; t < 4; t++) {
            const int i = 4 * g + 1 + t;
            if (i >= WPT) continue;                  /* g=3, t=3 */
            const float vo = ov[t];
            const float vn = nv[t];
            sum += vn - vo;
            sq  += fmaf(vn, vn, -vo * vo);
            float dlo, dhi;
            UNPACK2(dlo, dhi, dot2[i]);
            const float den = sq - sum * sum * (1.0f / KS);
            const float scv = (dlo + dhi) * rsqrtf(den);  /* NaN on pad: guarded */
            const int   w   = base + i;
            if (w < NWIN && scv > best) { best = scv; bidx = w; }  /* strict > */
        }
    }

    // ---- argmax: warp shfl -> cross-warp ----
    #pragma unroll
    for (int off = 16; off > 0; off >>= 1) {
        const float so = __shfl_xor_sync(0xffffffffu, best, off);
        const int   io = __shfl_xor_sync(0xffffffffu, bidx, off);
        if (so > best || (so == best && io < bidx)) { best = so; bidx = io; }
    }
    if (lane == 0) { redS[wid] = best; redI[wid] = bidx; }
    __syncthreads();

    if (wid == 0) {
        best = redS[lane];               /* NT/32 == 16 entries */
        bidx = redI[lane];
        if (lane >= NT / 32) { best = -INFINITY; bidx = NWIN; }
        #pragma unroll
        for (int off = 16; off > 0; off >>= 1) {
            const float so = __shfl_xor_sync(0xffffffffu, best, off);
            const int   io = __shfl_xor_sync(0xffffffffu, bidx, off);
            if (so > best || (so == best && io < bidx)) { best = so; bidx = io; }
        }
        if (lane == 0) widx_sh = bidx;
    }
    __syncthreads();
    const int widx = widx_sh;

    // ---- tiny affine head (shapelet straight from gmem, L1/L2-hot) ----
    if (tid < EOUT) {
        const float* segf = (const float*)seg4;
        float acc = l1_b[tid] - l2_b[tid];
        const float* w1 = l1_w + tid * KS;
        const float* w2 = l2_w + tid * KS;
        #pragma unroll
        for (int k = 0; k < KS; k++) {
            const int e = widx + k;
            acc = fmaf(segf[SKEW(e >> 2) * 4 + (e & 3)], w1[k], acc);
            acc = fmaf(-shp[k],                          w2[k], acc);
        }
        out[b * EOUT + tid] = acc;
    }
}

extern "C" void kernel_launch(void* const* d_in, const int* in_sizes, int n_in,
                              void* d_out, int out_size)
{
    const float* x    = (const float*)d_in[0];
    const float* shp  = (const float*)d_in[1];
    const float* l1_w = (const float*)d_in[2];
    const float* l1_b = (const float*)d_in[3];
    const float* l2_w = (const float*)d_in[4];
    const float* l2_b = (const float*)d_in[5];
    float* out = (float*)d_out;

    shapelet_kernel<<<BATCH, NT>>>(x, shp, l1_w, l1_b, l2_w, l2_b, out);
}